// round 8
// baseline (speedup 1.0000x reference)
#include <cuda_runtime.h>
#include <cuda_bf16.h>
#include <cuda_fp16.h>
#include <cstdint>

// Problem constants
constexpr int Bb   = 2;
constexpr int Ss   = 2048;
constexpr int Cin  = 512;
constexpr int Cout = 768;
constexpr int KW   = 31;
constexpr int PAD  = 15;            // (KW-1)/2
constexpr int Gg   = 6;
constexpr int Dd   = Cout / Gg;     // 128
constexpr int SP   = Ss + 2 * PAD;  // 2078
constexpr int Mtot = Bb * Ss;       // 4096
constexpr int NX   = Mtot * Cin;
constexpr int NW   = Cout * Cin;
constexpr int KP   = Cin / 2;       // 256 k-pairs per row
constexpr int NQR  = 186;           // G*KW
constexpr int NQRP = 192;           // padded to 3 N-tiles of 64

// Scratch (allocation-free rule: __device__ globals)
__device__ float g_Q[Bb * Ss * Cout];
__device__ float g_K[Bb * SP * Cout];
__device__ float g_V[Bb * SP * Cout];
__device__ float g_M[NQRP * Cin];        // M[(g,kk)][c] = sum_d Wq[gd][c]*rel[gd][kk]
__device__ float g_dotQR[Mtot * NQRP];   // q . rel term per (s,(g,kk))
__device__ uint2 g_xp[NX / 2];           // (hi half2, lo half2) of x*0.25
__device__ uint2 g_wp[3][NW / 2];        // same for W*4
__device__ uint2 g_mp[NQRP * KP];        // same for M*4

// ---------------------------------------------------------------------------
// fp16 split + mma helpers (sm_80+ PTX; valid at plain sm_100 target)
// ---------------------------------------------------------------------------
__device__ __forceinline__ uint2 split_pair_f16(float v0, float v1) {
    __half h0 = __float2half_rn(v0), h1 = __float2half_rn(v1);
    float r0 = v0 - __half2float(h0);
    float r1 = v1 - __half2float(h1);
    __half l0 = __float2half_rn(r0), l1 = __float2half_rn(r1);
    uint2 u;
    __half2 hh = __halves2half2(h0, h1);
    __half2 ll = __halves2half2(l0, l1);
    u.x = *reinterpret_cast<uint32_t*>(&hh);
    u.y = *reinterpret_cast<uint32_t*>(&ll);
    return u;
}

__device__ __forceinline__ void mma_f16(float* c, const uint32_t* a,
                                        const uint32_t* b) {
    asm volatile(
        "mma.sync.aligned.m16n8k16.row.col.f32.f16.f16.f32 "
        "{%0,%1,%2,%3}, {%4,%5,%6,%7}, {%8,%9}, {%0,%1,%2,%3};"
        : "+f"(c[0]), "+f"(c[1]), "+f"(c[2]), "+f"(c[3])
        : "r"(a[0]), "r"(a[1]), "r"(a[2]), "r"(a[3]),
          "r"(b[0]), "r"(b[1]));
}

// ---------------------------------------------------------------------------
// M kernel: M[n=(g,kk)][c] = sum_{d<128} Wq[g*128+d][c] * rel[g*128+d][kk].
// grid (2, 192), block 256. Warp reads: Wq coalesced, rel broadcast.
// ---------------------------------------------------------------------------
__global__ void mmat_kernel(const float* __restrict__ Wq,
                            const float* __restrict__ rel) {
    const int c = blockIdx.x * 256 + threadIdx.x;
    const int n = blockIdx.y;
    float acc = 0.0f;
    if (n < NQR) {
        const int g = n / KW, kk = n - g * KW;
        const float* wp = Wq + (size_t)(g * Dd) * Cin + c;
        const float* rp = rel + (size_t)(g * Dd) * KW + kk;
#pragma unroll 4
        for (int d = 0; d < Dd; d++)
            acc = fmaf(wp[(size_t)d * Cin], rp[(size_t)d * KW], acc);
    }
    g_M[(size_t)n * Cin + c] = acc;
}

// ---------------------------------------------------------------------------
// Split + prep: fp16 hi/lo pair planes for x (*0.25), W (*4), M (*4);
// zero the pad rows of g_K / g_V.
// ---------------------------------------------------------------------------
__global__ void split_prep_kernel(const float* __restrict__ x,
                                  const float* __restrict__ Wq,
                                  const float* __restrict__ Wk,
                                  const float* __restrict__ Wv) {
    const int stride = gridDim.x * blockDim.x;
    const int i0 = blockIdx.x * blockDim.x + threadIdx.x;

    for (int t = i0; t < NX / 2; t += stride) {
        const float2 v = *(const float2*)(x + 2 * t);
        g_xp[t] = split_pair_f16(v.x * 0.25f, v.y * 0.25f);
    }
    const float* Ws[3] = {Wq, Wk, Wv};
#pragma unroll
    for (int m = 0; m < 3; m++) {
        const float* W = Ws[m];
        for (int t = i0; t < NW / 2; t += stride) {
            const float2 v = *(const float2*)(W + 2 * t);
            g_wp[m][t] = split_pair_f16(v.x * 4.0f, v.y * 4.0f);
        }
    }
    for (int t = i0; t < NQRP * KP; t += stride) {
        const float2 v = *(const float2*)(g_M + 2 * t);
        g_mp[t] = split_pair_f16(v.x * 4.0f, v.y * 4.0f);
    }
    const int padRows = 2 * PAD;
    const int totZero = Bb * padRows * Cout;
    for (int t = i0; t < totZero; t += stride) {
        int r = t / Cout;
        int c = t - r * Cout;
        int b  = r / padRows;
        int rr = r - b * padRows;
        int row = b * SP + (rr < PAD ? rr : (PAD + Ss + rr - PAD));
        g_K[row * Cout + c] = 0.0f;
        g_V[row * Cout + c] = 0.0f;
    }
}

// ---------------------------------------------------------------------------
// fp16x3 GEMM via mma.sync.m16n8k16. z = 0..2: Q/K/V projections (N=768).
// z = 3: dotQR = x @ M^T (N=192; only blockIdx.x < 3 valid).
// CTA tile 128x64, K-chunk 32 floats, double-buffered smem, pitch 20.
// ---------------------------------------------------------------------------
constexpr int APITCH = 20;
constexpr int AS_ELEMS = 2 * 128 * APITCH;
constexpr int BS_ELEMS = 2 * 64 * APITCH;
constexpr int GEMM_SMEM = (AS_ELEMS + BS_ELEMS) * 8;   // 61440 B
constexpr int NKT = Cin / 32;                          // 16 K-chunks

__global__ void __launch_bounds__(256, 2) proj_gemm_mma(int unused)
{
    extern __shared__ uint2 smemBuf[];
    uint2* As2 = smemBuf;
    uint2* Bs2 = smemBuf + AS_ELEMS;

    const int mat = blockIdx.z;
    if (mat == 3 && blockIdx.x >= NQRP / 64) return;
    const uint2* __restrict__ Wh = (mat < 3) ? g_wp[mat] : g_mp;
    const int bn = blockIdx.x * 64;
    const int bm = blockIdx.y * 128;
    const int tid  = threadIdx.x;
    const int wid  = tid >> 5;
    const int lane = tid & 31;
    const int wm = wid >> 1;
    const int wn = wid & 1;
    const int r4 = lane >> 2;
    const int c4 = lane & 3;

    int arow[4], akp[4], brow[2], bkp[2];
#pragma unroll
    for (int i = 0; i < 4; i++) {
        const int idx = i * 256 + tid;
        arow[i] = idx >> 3; akp[i] = (idx & 7) * 2;
    }
#pragma unroll
    for (int i = 0; i < 2; i++) {
        const int idx = i * 256 + tid;
        brow[i] = idx >> 3; bkp[i] = (idx & 7) * 2;
    }

    float acc[2][4][4];
#pragma unroll
    for (int mt = 0; mt < 2; mt++)
#pragma unroll
        for (int nt = 0; nt < 4; nt++)
#pragma unroll
            for (int e = 0; e < 4; e++) acc[mt][nt][e] = 0.0f;

    uint4 pa[4], pb[2];
#pragma unroll
    for (int i = 0; i < 4; i++)
        pa[i] = *(const uint4*)&g_xp[(size_t)(bm + arow[i]) * KP + akp[i]];
#pragma unroll
    for (int i = 0; i < 2; i++)
        pb[i] = *(const uint4*)&Wh[(size_t)(bn + brow[i]) * KP + bkp[i]];
#pragma unroll
    for (int i = 0; i < 4; i++)
        *(uint4*)&As2[arow[i] * APITCH + akp[i]] = pa[i];
#pragma unroll
    for (int i = 0; i < 2; i++)
        *(uint4*)&Bs2[brow[i] * APITCH + bkp[i]] = pb[i];
    __syncthreads();

    int buf = 0;
    for (int kt = 0; kt < NKT; kt++) {
        if (kt < NKT - 1) {
            const int k0 = (kt + 1) * 16;
#pragma unroll
            for (int i = 0; i < 4; i++)
                pa[i] = *(const uint4*)&g_xp[(size_t)(bm + arow[i]) * KP + k0 + akp[i]];
#pragma unroll
            for (int i = 0; i < 2; i++)
                pb[i] = *(const uint4*)&Wh[(size_t)(bn + brow[i]) * KP + k0 + bkp[i]];
        }

        const uint2* Ab = As2 + buf * 128 * APITCH;
        const uint2* Bbf = Bs2 + buf * 64 * APITCH;
#pragma unroll
        for (int ks = 0; ks < 2; ks++) {
            const int kp = ks * 8 + c4;
            uint2 aF[2][4], bF[4][2];
#pragma unroll
            for (int mt = 0; mt < 2; mt++) {
                const uint2* ap = Ab + (wm * 32 + mt * 16 + r4) * APITCH + kp;
                aF[mt][0] = ap[0];
                aF[mt][1] = ap[8 * APITCH];
                aF[mt][2] = ap[4];
                aF[mt][3] = ap[8 * APITCH + 4];
            }
#pragma unroll
            for (int nt = 0; nt < 4; nt++) {
                const uint2* bp = Bbf + (wn * 32 + nt * 8 + r4) * APITCH + kp;
                bF[nt][0] = bp[0];
                bF[nt][1] = bp[4];
            }
#pragma unroll
            for (int mt = 0; mt < 2; mt++) {
                const uint32_t aH[4] = {aF[mt][0].x, aF[mt][1].x, aF[mt][2].x, aF[mt][3].x};
                const uint32_t aL[4] = {aF[mt][0].y, aF[mt][1].y, aF[mt][2].y, aF[mt][3].y};
#pragma unroll
                for (int nt = 0; nt < 4; nt++) {
                    const uint32_t bH[2] = {bF[nt][0].x, bF[nt][1].x};
                    const uint32_t bL[2] = {bF[nt][0].y, bF[nt][1].y};
                    mma_f16(acc[mt][nt], aH, bH);
                    mma_f16(acc[mt][nt], aL, bH);
                    mma_f16(acc[mt][nt], aH, bL);
                }
            }
        }

        if (kt < NKT - 1) {
            const int nb = buf ^ 1;
            uint2* Aw = As2 + nb * 128 * APITCH;
            uint2* Bw = Bs2 + nb * 64 * APITCH;
#pragma unroll
            for (int i = 0; i < 4; i++)
                *(uint4*)&Aw[arow[i] * APITCH + akp[i]] = pa[i];
#pragma unroll
            for (int i = 0; i < 2; i++)
                *(uint4*)&Bw[brow[i] * APITCH + bkp[i]] = pb[i];
            __syncthreads();
            buf = nb;
        }
    }

#pragma unroll
    for (int mt = 0; mt < 2; mt++) {
        const int m = bm + wm * 32 + mt * 16 + r4;
        float *row0, *row1;
        if (mat == 0) {
            row0 = g_Q + (size_t)m * Cout;
            row1 = g_Q + (size_t)(m + 8) * Cout;
        } else if (mat == 3) {
            row0 = g_dotQR + (size_t)m * NQRP;
            row1 = row0 + (size_t)8 * NQRP;
        } else {
            float* base = (mat == 1) ? g_K : g_V;
            const int b0 = m >> 11, s0 = m & 2047;
            row0 = base + (size_t)(b0 * SP + s0 + PAD) * Cout;
            row1 = row0 + (size_t)8 * Cout;
        }
#pragma unroll
        for (int nt = 0; nt < 4; nt++) {
            const int n = bn + wn * 32 + nt * 8 + 2 * c4;
            *(float2*)(row0 + n) = make_float2(acc[mt][nt][0], acc[mt][nt][1]);
            *(float2*)(row1 + n) = make_float2(acc[mt][nt][2], acc[mt][nt][3]);
        }
    }
}

// ---------------------------------------------------------------------------
// Attention v2: one warp per 4 consecutive s of a (b,g). Shared k/v rows in
// registers across the 4 tasks; rel term pre-computed (g_dotQR).
// grid = (Ss/32, Gg, Bb), 256 threads (8 warps x 4 s = 32 s per block).
// ---------------------------------------------------------------------------
__global__ void __launch_bounds__(256) attn_kernel(
    float* __restrict__ out, float* __restrict__ attnOut)
{
    const unsigned FULL = 0xffffffffu;
    const int warp = threadIdx.x >> 5;
    const int lane = threadIdx.x & 31;
    const int s0 = blockIdx.x * 32 + warp * 4;
    const int g = blockIdx.y;
    const int b = blockIdx.z;

    float4 q[4];
    float dq[4];
    float myE[4];
#pragma unroll
    for (int i = 0; i < 4; i++) {
        q[i] = *(const float4*)(g_Q + (size_t)(b * Ss + s0 + i) * Cout
                                + g * Dd + lane * 4);
        dq[i] = (lane < KW)
              ? g_dotQR[(size_t)(b * Ss + s0 + i) * NQRP + g * KW + lane]
              : 0.0f;
        myE[i] = -3.4e38f;
    }

    const float* kbase = g_K + (size_t)(b * SP + s0) * Cout + g * Dd + lane * 4;
    const float* vbase = g_V + (size_t)(b * SP + s0) * Cout + g * Dd + lane * 4;

    // Energy: 34 shared k rows serve 4 tasks.
    for (int r = 0; r < KW + 3; r++) {
        const float4 kv = *(const float4*)(kbase + (size_t)r * Cout);
#pragma unroll
        for (int i = 0; i < 4; i++) {
            const int tap = r - i;
            if (tap >= 0 && tap < KW) {            // warp-uniform
                float e = q[i].x * kv.x + q[i].y * kv.y
                        + q[i].z * kv.z + q[i].w * kv.w;
#pragma unroll
                for (int o = 16; o; o >>= 1) e += __shfl_xor_sync(FULL, e, o);
                if (lane == tap) myE[i] = e + dq[i];
            }
        }
    }

    // Softmax per task (lane kk holds energy kk).
    float a[4];
#pragma unroll
    for (int i = 0; i < 4; i++) {
        float m = myE[i];
#pragma unroll
        for (int o = 16; o; o >>= 1) m = fmaxf(m, __shfl_xor_sync(FULL, m, o));
        float p = (lane < KW) ? __expf(myE[i] - m) : 0.0f;
        float sum = p;
#pragma unroll
        for (int o = 16; o; o >>= 1) sum += __shfl_xor_sync(FULL, sum, o);
        a[i] = p / sum;
        if (lane < KW)
            attnOut[((size_t)(b * Ss + s0 + i) * Gg + g) * KW + lane] = a[i];
    }

    // Weighted V: 34 shared v rows serve 4 tasks.
    float4 acc[4];
#pragma unroll
    for (int i = 0; i < 4; i++) acc[i] = make_float4(0.f, 0.f, 0.f, 0.f);
    for (int r = 0; r < KW + 3; r++) {
        const float4 vv = *(const float4*)(vbase + (size_t)r * Cout);
#pragma unroll
        for (int i = 0; i < 4; i++) {
            const int tap = r - i;
            if (tap >= 0 && tap < KW) {
                const float ak = __shfl_sync(FULL, a[i], tap);
                acc[i].x = fmaf(ak, vv.x, acc[i].x);
                acc[i].y = fmaf(ak, vv.y, acc[i].y);
                acc[i].z = fmaf(ak, vv.z, acc[i].z);
                acc[i].w = fmaf(ak, vv.w, acc[i].w);
            }
        }
    }
#pragma unroll
    for (int i = 0; i < 4; i++)
        *(float4*)(out + (size_t)(b * Ss + s0 + i) * Cout + g * Dd + lane * 4)
            = acc[i];
}

// Dummy: keeps proj_gemm_mma at overall launch slot #4 (the slot ncu's
// capture empirically lands on), so next round gets the GEMM profile.
__global__ void dummy_kernel() {}

// ---------------------------------------------------------------------------
extern "C" void kernel_launch(void* const* d_in, const int* in_sizes, int n_in,
                              void* d_out, int out_size)
{
    const float* x   = (const float*)d_in[0];
    const float* Wq  = (const float*)d_in[1];
    const float* Wk  = (const float*)d_in[2];
    const float* Wv  = (const float*)d_in[3];
    const float* rel = (const float*)d_in[4];

    float* out  = (float*)d_out;                       // [B,S,OUT] fp32
    float* attn = out + (size_t)Bb * Ss * Cout;        // [B,S,G,K] fp32

    cudaFuncSetAttribute(proj_gemm_mma,
                         cudaFuncAttributeMaxDynamicSharedMemorySize, GEMM_SMEM);

    mmat_kernel<<<dim3(2, NQRP), 256>>>(Wq, rel);                    // #1
    split_prep_kernel<<<1024, 256>>>(x, Wq, Wk, Wv);                 // #2
    dummy_kernel<<<1, 32>>>();                                       // #3
    proj_gemm_mma<<<dim3(Cout / 64, Mtot / 128, 4), 256, GEMM_SMEM>>>(0); // #4
    attn_kernel<<<dim3(Ss / 32, Gg, Bb), 256>>>(out, attn);          // #5
}